// round 4
// baseline (speedup 1.0000x reference)
#include <cuda_runtime.h>
#include <math.h>

#define N_NODES 15
#define EMBED   2048
#define F1      1024
#define F2      512
#define NE      120
#define H1N     480
#define H2N     1920
#define HN      (N_NODES*EMBED)   // 30720

// ---------- scratch (device globals; no allocation) ----------
__device__ float g_h1[H1N];
__device__ float g_h2[H2N];            // pre-relu accum, init to b2
__device__ float g_H[HN];              // h@W3+b3, init to b3
__device__ float g_HW1[N_NODES*F1];
__device__ float g_X1[N_NODES*F1];
__device__ float g_HW2[N_NODES*F2];
__device__ float g_X2[N_NODES*F2];
__device__ float g_m[F2];              // column mean of X2
__device__ float g_ctx[F2];            // accumulator for m@attW

// ---------- K0: init accumulators ----------
__global__ void k_init(const float* __restrict__ b2, const float* __restrict__ b3) {
    int i = blockIdx.x * blockDim.x + threadIdx.x;   // 120*256 = 30720 threads
    if (i < HN)            g_H[i]   = b3[i];
    if (i < H2N)           g_h2[i]  = b2[i];
    if (i < N_NODES * F1)  g_HW1[i] = 0.f;
    if (i < N_NODES * F2)  g_HW2[i] = 0.f;
    if (i < F2)            g_ctx[i] = 0.f;
}

// ---------- K1: h1 = relu(f @ W1 + b1)  [480] ----------
__global__ void k_mlp1(const float* __restrict__ f, const float* __restrict__ W1,
                       const float* __restrict__ b1) {
    __shared__ float sf[N_NODES];
    int t = threadIdx.x;                 // 480 threads
    if (t < N_NODES) sf[t] = f[t];
    __syncthreads();
    float a = b1[t];
#pragma unroll
    for (int i = 0; i < N_NODES; i++) a += sf[i] * W1[i * H1N + t];
    g_h1[t] = fmaxf(a, 0.f);
}

// ---------- K2: h2 += h1 @ W2 (split-K), bias pre-loaded ----------
__global__ void k_mlp2(const float* __restrict__ W2) {
    __shared__ float sh[120];
    int t = threadIdx.x;                 // 128 threads
    int j = blockIdx.x * 128 + t;        // 15 blocks -> 1920 cols
    int k0 = blockIdx.y * 120;           // 4 k-splits
    if (t < 120) sh[t] = g_h1[k0 + t];
    __syncthreads();
    float a = 0.f;
#pragma unroll 4
    for (int kk = 0; kk < 120; kk++) a += sh[kk] * W2[(k0 + kk) * H2N + j];
    atomicAdd(&g_h2[j], a);
}

// ---------- K3: H += relu(h2) @ W3 (split-K, float4) -- THE big one ----------
__global__ void __launch_bounds__(256) k_mlp3(const float4* __restrict__ W3v) {
    __shared__ float sh[120];
    int t = threadIdx.x;
    int k0 = blockIdx.y * 120;           // 16 k-splits over 1920
    if (t < 120) sh[t] = fmaxf(g_h2[k0 + t], 0.f);
    __syncthreads();
    int c = blockIdx.x * 256 + t;        // 30 blocks -> 7680 float4 columns
    const float4* p = W3v + (size_t)k0 * 7680 + c;
    float4 acc = make_float4(0.f, 0.f, 0.f, 0.f);
#pragma unroll 4
    for (int kk = 0; kk < 120; kk++) {
        float4 w = p[(size_t)kk * 7680];
        float h = sh[kk];
        acc.x += h * w.x; acc.y += h * w.y; acc.z += h * w.z; acc.w += h * w.w;
    }
    float* o = g_H + 4 * c;
    atomicAdd(o + 0, acc.x); atomicAdd(o + 1, acc.y);
    atomicAdd(o + 2, acc.z); atomicAdd(o + 3, acc.w);
}

// ---------- K4/K6: OUT += X[15,K] @ W[K,N]  (split-K, 15 row-accumulators) ----------
template <int L>   // L=0: g_H(K=2048)->g_HW1(N=1024) ; L=1: g_X1(K=1024)->g_HW2(N=512)
__global__ void __launch_bounds__(256) k_gemm(const float* __restrict__ W) {
    constexpr int K = (L == 0) ? 2048 : 1024;
    constexpr int N = (L == 0) ? 1024 : 512;
    const float* X  = (L == 0) ? g_H : g_X1;
    float* OUT      = (L == 0) ? g_HW1 : g_HW2;

    __shared__ float Xt[N_NODES * 32];
    int t = threadIdx.x;
    int k0 = blockIdx.y * 32;
    for (int idx = t; idx < N_NODES * 32; idx += 256) {
        int i = idx >> 5, kk = idx & 31;
        Xt[idx] = X[i * K + k0 + kk];
    }
    __syncthreads();
    int j = blockIdx.x * 256 + t;
    float acc[N_NODES];
#pragma unroll
    for (int i = 0; i < N_NODES; i++) acc[i] = 0.f;
    for (int kk = 0; kk < 32; kk++) {
        float w = W[(size_t)(k0 + kk) * N + j];
#pragma unroll
        for (int i = 0; i < N_NODES; i++) acc[i] += Xt[i * 32 + kk] * w;
    }
#pragma unroll
    for (int i = 0; i < N_NODES; i++) atomicAdd(&OUT[i * N + j], acc[i]);
}

// ---------- K5/K7: normalized adjacency aggregation (+bias, relu / mean) ----------
template <int L>   // L=0: HW1->X1, N=1024, relu ; L=1: HW2->X2, N=512, no relu, + mean
__global__ void __launch_bounds__(128) k_agg(const int* __restrict__ eidx,
                                             const float* __restrict__ bias) {
    constexpr int Nd = (L == 0) ? 1024 : 512;
    const float* HW = (L == 0) ? g_HW1 : g_HW2;
    float* XOUT     = (L == 0) ? g_X1 : g_X2;

    __shared__ int   se[NE], de[NE];
    __shared__ float deg[N_NODES], dinv[N_NODES], nrm[NE];
    __shared__ float hws[N_NODES][128];
    __shared__ float outs[N_NODES][128];

    int t = threadIdx.x;
    if (t < NE) { se[t] = eidx[t]; de[t] = eidx[NE + t]; }
    if (t < N_NODES) deg[t] = 1.f;               // self loop
    __syncthreads();
    if (t < NE) atomicAdd(&deg[de[t]], 1.f);
    __syncthreads();
    if (t < N_NODES) dinv[t] = rsqrtf(deg[t]);
    __syncthreads();
    if (t < NE) nrm[t] = dinv[se[t]] * dinv[de[t]];

    int j = blockIdx.x * 128 + t;
#pragma unroll
    for (int i = 0; i < N_NODES; i++) hws[i][t] = HW[i * Nd + j];
    __syncthreads();
#pragma unroll
    for (int i = 0; i < N_NODES; i++) outs[i][t] = hws[i][t] * dinv[i] * dinv[i];
    for (int e = 0; e < NE; e++)
        outs[de[e]][t] += hws[se[e]][t] * nrm[e];

    float b = bias[j];
    float s = 0.f;
#pragma unroll
    for (int i = 0; i < N_NODES; i++) {
        float v = outs[i][t] + b;
        if (L == 0) v = fmaxf(v, 0.f);
        XOUT[i * Nd + j] = v;
        s += v;
    }
    if (L == 1) g_m[j] = s * (1.f / 15.f);
}

// ---------- K8: g_ctx += m @ attW (split-K) ----------
__global__ void __launch_bounds__(256) k_ctx(const float* __restrict__ attW) {
    __shared__ float sm[64];
    int t = threadIdx.x;
    int k0 = blockIdx.y * 64;            // 8 k-splits over 512
    if (t < 64) sm[t] = g_m[k0 + t];
    __syncthreads();
    int j = blockIdx.x * 256 + t;        // 2 blocks -> 512 cols
    float a = 0.f;
#pragma unroll 4
    for (int kk = 0; kk < 64; kk++) a += sm[kk] * attW[(size_t)(k0 + kk) * F2 + j];
    atomicAdd(&g_ctx[j], a);
}

// ---------- K9: attention pool + fc + softmax + loss ----------
__global__ void __launch_bounds__(512) k_final(const float* __restrict__ fcW,
                                               const float* __restrict__ fcb,
                                               const float* __restrict__ target,
                                               float* __restrict__ out) {
    __shared__ float ctx_s[F2];
    __shared__ float sc[N_NODES];
    __shared__ float lg[3];
    int t = threadIdx.x;                 // 512 threads
    ctx_s[t] = tanhf(g_ctx[t]);
    if (t < 3) lg[t] = fcb[t];
    __syncthreads();

    int w = t >> 5, l = t & 31;          // 16 warps
    if (w < N_NODES) {
        float v = 0.f;
#pragma unroll
        for (int q = 0; q < 16; q++) {
            int j = l + 32 * q;
            v += g_X2[w * F2 + j] * ctx_s[j];
        }
#pragma unroll
        for (int o = 16; o > 0; o >>= 1) v += __shfl_xor_sync(0xffffffffu, v, o);
        if (l == 0) sc[w] = 1.f / (1.f + expf(-v));
    }
    __syncthreads();

    float rep = 0.f;
#pragma unroll
    for (int i = 0; i < N_NODES; i++) rep += g_X2[i * F2 + t] * sc[i];

    float p0 = rep * fcW[t * 3 + 0];
    float p1 = rep * fcW[t * 3 + 1];
    float p2 = rep * fcW[t * 3 + 2];
#pragma unroll
    for (int o = 16; o > 0; o >>= 1) {
        p0 += __shfl_xor_sync(0xffffffffu, p0, o);
        p1 += __shfl_xor_sync(0xffffffffu, p1, o);
        p2 += __shfl_xor_sync(0xffffffffu, p2, o);
    }
    if (l == 0) { atomicAdd(&lg[0], p0); atomicAdd(&lg[1], p1); atomicAdd(&lg[2], p2); }
    __syncthreads();

    if (t == 0) {
        float l0 = lg[0], l1 = lg[1], l2 = lg[2];
        float mx = fmaxf(l0, fmaxf(l1, l2));
        float e0 = expf(l0 - mx), e1 = expf(l1 - mx), e2 = expf(l2 - mx);
        float s = e0 + e1 + e2;
        float t0 = target[0], t1 = target[1], t2 = target[2];
        int cls = 0; float tm = t0;
        if (t1 > tm) { tm = t1; cls = 1; }
        if (t2 > tm) { tm = t2; cls = 2; }
        float lcls = (cls == 0) ? l0 : ((cls == 1) ? l1 : l2);
        out[0] = -(lcls - mx - logf(s));    // loss
        out[1] = e0 / s; out[2] = e1 / s; out[3] = e2 / s;  // predictions
    }
}

// ---------- host ----------
extern "C" void kernel_launch(void* const* d_in, const int* in_sizes, int n_in,
                              void* d_out, int out_size) {
    const float* f      = (const float*)d_in[0];
    const int*   eidx   = (const int*)  d_in[1];
    const float* target = (const float*)d_in[2];
    const float* W1     = (const float*)d_in[3];
    const float* b1     = (const float*)d_in[4];
    const float* W2     = (const float*)d_in[5];
    const float* b2     = (const float*)d_in[6];
    const float* W3     = (const float*)d_in[7];
    const float* b3     = (const float*)d_in[8];
    const float* gW1    = (const float*)d_in[9];
    const float* gb1    = (const float*)d_in[10];
    const float* gW2    = (const float*)d_in[11];
    const float* gb2    = (const float*)d_in[12];
    const float* attW   = (const float*)d_in[13];
    const float* fcW    = (const float*)d_in[14];
    const float* fcb    = (const float*)d_in[15];
    float* out = (float*)d_out;

    k_init<<<120, 256>>>(b2, b3);
    k_mlp1<<<1, 480>>>(f, W1, b1);
    k_mlp2<<<dim3(15, 4), 128>>>(W2);
    k_mlp3<<<dim3(30, 16), 256>>>((const float4*)W3);
    k_gemm<0><<<dim3(4, 64), 256>>>(gW1);
    k_agg<0><<<8, 128>>>(eidx, gb1);
    k_gemm<1><<<dim3(2, 32), 256>>>(gW2);
    k_agg<1><<<4, 128>>>(eidx, gb2);
    k_ctx<<<dim3(2, 8), 256>>>(attW);
    k_final<<<1, 512>>>(fcW, fcb, target, out);
}

// round 5
// speedup vs baseline: 1.3863x; 1.3863x over previous
#include <cuda_runtime.h>
#include <math.h>

#define N_NODES 15
#define EMBED   2048
#define F1      1024
#define F2      512
#define NE      120
#define H1N     480
#define H2N     1920
#define HN      (N_NODES*EMBED)   // 30720

// ---------- scratch (device globals; no allocation) ----------
__device__ float g_h2[H2N];            // post-relu hidden 2
__device__ float g_H[HN];              // h@W3+b3 accumulator (init b3 in k_pre)
__device__ float g_HW1[N_NODES*F1];
__device__ float g_X1[N_NODES*F1];
__device__ float g_HW2[N_NODES*F2];
__device__ float g_X2[N_NODES*F2];
__device__ float g_m[F2];              // column mean of X2
__device__ float g_ctx[F2];            // accumulator for m@attW
__device__ int   g_cnt1[4];            // arrival counters for gcn1 column tiles
__device__ int   g_cnt2[2];            // arrival counters for gcn2 column tiles
__device__ float g_sink;               // DCE-prevention for prefetch

// =====================================================================
// K_PRE: fused  init + MLP1 + MLP2  (blocks 0..59)
//        and    accumulator init + L2 prefetch (blocks 60..147)
// =====================================================================
__global__ void __launch_bounds__(128) k_pre(
    const float* __restrict__ f,  const float* __restrict__ W1, const float* __restrict__ b1,
    const float* __restrict__ W2, const float* __restrict__ b2, const float* __restrict__ b3,
    const float* __restrict__ gW1, const float* __restrict__ gW2,
    const float* __restrict__ attW, const float* __restrict__ fcW) {
    int bx = blockIdx.x, t = threadIdx.x;
    if (bx < 60) {
        // --- each block redundantly computes h1[480], then 32 h2 columns ---
        __shared__ float sf[N_NODES];
        __shared__ float sh1[H1N];
        __shared__ float red[4][32];
        if (t < N_NODES) sf[t] = f[t];
        __syncthreads();
        for (int j = t; j < H1N; j += 128) {
            float a = b1[j];
#pragma unroll
            for (int i = 0; i < N_NODES; i++) a += sf[i] * W1[i * H1N + j];
            sh1[j] = fmaxf(a, 0.f);
        }
        __syncthreads();
        int col = bx * 32 + (t & 31);
        int s   = t >> 5;                 // 4-way k-split of K=480
        int k0  = s * 120;
        float a = 0.f;
#pragma unroll 8
        for (int kk = 0; kk < 120; kk++)
            a += sh1[k0 + kk] * W2[(k0 + kk) * H2N + col];
        red[s][t & 31] = a;
        __syncthreads();
        if (s == 0) {
            float v = a + red[1][t] + red[2][t] + red[3][t] + b2[col];
            g_h2[col] = fmaxf(v, 0.f);    // relu here; mlp3 reads directly
        }
    } else {
        // --- inits + warm L2 with downstream weights ---
        int gt = (bx - 60) * 128 + t;     // 0 .. 11263
        const int GS = 88 * 128;
        for (int i = gt; i < HN; i += GS)            g_H[i]   = b3[i];
        for (int i = gt; i < N_NODES * F1; i += GS)  g_HW1[i] = 0.f;
        for (int i = gt; i < N_NODES * F2; i += GS)  g_HW2[i] = 0.f;
        if (gt < F2) g_ctx[gt] = 0.f;
        if (gt < 4)  g_cnt1[gt] = 0;
        if (gt < 2)  g_cnt2[gt] = 0;

        float4 av = make_float4(0.f, 0.f, 0.f, 0.f);
        const float4* p1 = (const float4*)gW1;   // 524288 float4
#pragma unroll 4
        for (int i = gt; i < 524288; i += GS) {
            float4 v = p1[i]; av.x += v.x; av.y += v.y; av.z += v.z; av.w += v.w;
        }
        const float4* p2 = (const float4*)gW2;   // 131072 float4
#pragma unroll 4
        for (int i = gt; i < 131072; i += GS) {
            float4 v = p2[i]; av.x += v.x; av.y += v.y; av.z += v.z; av.w += v.w;
        }
        const float4* p3 = (const float4*)attW;  // 65536 float4
#pragma unroll 4
        for (int i = gt; i < 65536; i += GS) {
            float4 v = p3[i]; av.x += v.x; av.y += v.y; av.z += v.z; av.w += v.w;
        }
        if (gt < F2 * 3) av.x += fcW[gt];
        float ssum = av.x + av.y + av.z + av.w;
        if (ssum == 1.234567e38f) g_sink = ssum;  // never true; blocks DCE
    }
}

// =====================================================================
// K_MLP3: g_H += relu(h2) @ W3   (split-K, float4, streaming loads)
// grid (60, 16) x 128 threads -> 960 blocks, smooth waves
// =====================================================================
__global__ void __launch_bounds__(128) k_mlp3(const float4* __restrict__ W3v) {
    __shared__ float sh[120];
    int t = threadIdx.x;
    int k0 = blockIdx.y * 120;
    if (t < 120) sh[t] = g_h2[k0 + t];
    __syncthreads();
    int c = blockIdx.x * 128 + t;            // 7680 float4 columns
    const float4* p = W3v + (size_t)k0 * 7680 + c;
    float4 acc = make_float4(0.f, 0.f, 0.f, 0.f);
#pragma unroll 8
    for (int kk = 0; kk < 120; kk++) {
        float4 w = __ldcs(p + (size_t)kk * 7680);   // evict-first: keep prefetch in L2
        float h = sh[kk];
        acc.x += h * w.x; acc.y += h * w.y; acc.z += h * w.z; acc.w += h * w.w;
    }
    float* o = g_H + 4 * c;
    atomicAdd(o + 0, acc.x); atomicAdd(o + 1, acc.y);
    atomicAdd(o + 2, acc.z); atomicAdd(o + 3, acc.w);
}

// =====================================================================
// K_GCN: fused  (X @ W split-K atomic)  +  adjacency aggregation
//        last k-split block per 256-col tile does the aggregation
// L=0: g_H[15,2048]@gW1 -> relu agg -> g_X1[15,1024]
// L=1: g_X1[15,1024]@gW2 -> agg (+mean) -> g_X2[15,512], g_m
// =====================================================================
template <int L>
__global__ void __launch_bounds__(256) k_gcn(const float* __restrict__ W,
                                             const float* __restrict__ bias,
                                             const int* __restrict__ eidx) {
    constexpr int K  = (L == 0) ? 2048 : 1024;
    constexpr int N  = (L == 0) ? 1024 : 512;
    constexpr int KS = (L == 0) ? 64 : 32;     // k per split (32 y-blocks)
    constexpr int NY = 32;
    const float* X  = (L == 0) ? g_H  : g_X1;
    float* OUT      = (L == 0) ? g_HW1 : g_HW2;
    float* XO       = (L == 0) ? g_X1 : g_X2;
    int*   cnt      = (L == 0) ? g_cnt1 : g_cnt2;

    __shared__ float Xt[N_NODES * KS];
    int t = threadIdx.x;
    int x = blockIdx.x;
    int k0 = blockIdx.y * KS;
    for (int idx = t; idx < N_NODES * KS; idx += 256) {
        int i = idx / KS, kk = idx % KS;
        Xt[idx] = X[i * K + k0 + kk];
    }
    __syncthreads();
    int j = x * 256 + t;
    float acc[N_NODES];
#pragma unroll
    for (int i = 0; i < N_NODES; i++) acc[i] = 0.f;
    for (int kk = 0; kk < KS; kk++) {
        float w = W[(size_t)(k0 + kk) * N + j];
#pragma unroll
        for (int i = 0; i < N_NODES; i++) acc[i] += Xt[i * KS + kk] * w;
    }
#pragma unroll
    for (int i = 0; i < N_NODES; i++) atomicAdd(&OUT[i * N + j], acc[i]);

    // ---- arrival: last block for this column tile aggregates ----
    __threadfence();
    __syncthreads();
    __shared__ int isLast;
    if (t == 0) isLast = (atomicAdd(&cnt[x], 1) == NY - 1);
    __syncthreads();
    if (!isLast) return;

    __shared__ int   se[NE], de[NE];
    __shared__ float degs[N_NODES], dinv[N_NODES], nrm[NE];
    __shared__ float hws[N_NODES][256];
    __shared__ float outs[N_NODES][256];
    if (t < NE) { se[t] = eidx[t]; de[t] = eidx[NE + t]; }
    if (t < N_NODES) degs[t] = 1.f;               // self loop
    __syncthreads();
    if (t < NE) atomicAdd(&degs[de[t]], 1.f);
    __syncthreads();
    if (t < N_NODES) dinv[t] = rsqrtf(degs[t]);
    __syncthreads();
    if (t < NE) nrm[t] = dinv[se[t]] * dinv[de[t]];

#pragma unroll
    for (int i = 0; i < N_NODES; i++) hws[i][t] = __ldcg(&OUT[i * N + j]);
    __syncthreads();
#pragma unroll
    for (int i = 0; i < N_NODES; i++) outs[i][t] = hws[i][t] * dinv[i] * dinv[i];
    for (int e = 0; e < NE; e++)
        outs[de[e]][t] += hws[se[e]][t] * nrm[e];

    float b = bias[j];
    float s = 0.f;
#pragma unroll
    for (int i = 0; i < N_NODES; i++) {
        float v = outs[i][t] + b;
        if (L == 0) v = fmaxf(v, 0.f);
        XO[i * N + j] = v;
        s += v;
    }
    if (L == 1) g_m[j] = s * (1.f / 15.f);
}

// =====================================================================
// K_CTX: g_ctx += m @ attW (split-K; attW is L2-resident from prefetch)
// =====================================================================
__global__ void __launch_bounds__(256) k_ctx(const float* __restrict__ attW) {
    __shared__ float sm[32];
    int t = threadIdx.x;
    int k0 = blockIdx.y * 32;                // 16 k-splits over 512
    if (t < 32) sm[t] = g_m[k0 + t];
    __syncthreads();
    int j = blockIdx.x * 256 + t;            // 2 blocks -> 512 cols
    float a = 0.f;
#pragma unroll
    for (int kk = 0; kk < 32; kk++) a += sm[kk] * attW[(size_t)(k0 + kk) * F2 + j];
    atomicAdd(&g_ctx[j], a);
}

// =====================================================================
// K_FINAL: attention pool + fc + softmax + loss
// =====================================================================
__global__ void __launch_bounds__(512) k_final(const float* __restrict__ fcW,
                                               const float* __restrict__ fcb,
                                               const float* __restrict__ target,
                                               float* __restrict__ out) {
    __shared__ float ctx_s[F2];
    __shared__ float sc[N_NODES];
    __shared__ float lg[3];
    int t = threadIdx.x;                 // 512 threads
    ctx_s[t] = tanhf(g_ctx[t]);
    if (t < 3) lg[t] = fcb[t];
    __syncthreads();

    int w = t >> 5, l = t & 31;          // 16 warps
    if (w < N_NODES) {
        float v = 0.f;
#pragma unroll
        for (int q = 0; q < 16; q++) {
            int j = l + 32 * q;
            v += g_X2[w * F2 + j] * ctx_s[j];
        }
#pragma unroll
        for (int o = 16; o > 0; o >>= 1) v += __shfl_xor_sync(0xffffffffu, v, o);
        if (l == 0) sc[w] = 1.f / (1.f + expf(-v));
    }
    __syncthreads();

    float rep = 0.f;
#pragma unroll
    for (int i = 0; i < N_NODES; i++) rep += g_X2[i * F2 + t] * sc[i];

    float p0 = rep * fcW[t * 3 + 0];
    float p1 = rep * fcW[t * 3 + 1];
    float p2 = rep * fcW[t * 3 + 2];
#pragma unroll
    for (int o = 16; o > 0; o >>= 1) {
        p0 += __shfl_xor_sync(0xffffffffu, p0, o);
        p1 += __shfl_xor_sync(0xffffffffu, p1, o);
        p2 += __shfl_xor_sync(0xffffffffu, p2, o);
    }
    if (l == 0) { atomicAdd(&lg[0], p0); atomicAdd(&lg[1], p1); atomicAdd(&lg[2], p2); }
    __syncthreads();

    if (t == 0) {
        float l0 = lg[0], l1 = lg[1], l2 = lg[2];
        float mx = fmaxf(l0, fmaxf(l1, l2));
        float e0 = expf(l0 - mx), e1 = expf(l1 - mx), e2 = expf(l2 - mx);
        float s = e0 + e1 + e2;
        float t0 = target[0], t1 = target[1], t2 = target[2];
        int cls = 0; float tm = t0;
        if (t1 > tm) { tm = t1; cls = 1; }
        if (t2 > tm) { tm = t2; cls = 2; }
        float lcls = (cls == 0) ? l0 : ((cls == 1) ? l1 : l2);
        out[0] = -(lcls - mx - logf(s));    // loss
        out[1] = e0 / s; out[2] = e1 / s; out[3] = e2 / s;  // predictions
    }
}

// ---------- host ----------
extern "C" void kernel_launch(void* const* d_in, const int* in_sizes, int n_in,
                              void* d_out, int out_size) {
    const float* f      = (const float*)d_in[0];
    const int*   eidx   = (const int*)  d_in[1];
    const float* target = (const float*)d_in[2];
    const float* W1     = (const float*)d_in[3];
    const float* b1     = (const float*)d_in[4];
    const float* W2     = (const float*)d_in[5];
    const float* b2     = (const float*)d_in[6];
    const float* W3     = (const float*)d_in[7];
    const float* b3     = (const float*)d_in[8];
    const float* gW1    = (const float*)d_in[9];
    const float* gb1    = (const float*)d_in[10];
    const float* gW2    = (const float*)d_in[11];
    const float* gb2    = (const float*)d_in[12];
    const float* attW   = (const float*)d_in[13];
    const float* fcW    = (const float*)d_in[14];
    const float* fcb    = (const float*)d_in[15];
    float* out = (float*)d_out;

    k_pre <<<148, 128>>>(f, W1, b1, W2, b2, b3, gW1, gW2, attW, fcW);
    k_mlp3<<<dim3(60, 16), 128>>>((const float4*)W3);
    k_gcn<0><<<dim3(4, 32), 256>>>(gW1, gb1, eidx);
    k_gcn<1><<<dim3(2, 32), 256>>>(gW2, gb2, eidx);
    k_ctx <<<dim3(2, 16), 256>>>(attW);
    k_final<<<1, 512>>>(fcW, fcb, target, out);
}

// round 6
// speedup vs baseline: 1.3953x; 1.0065x over previous
#include <cuda_runtime.h>
#include <math.h>

#define N_NODES 15
#define EMBED   2048
#define F1      1024
#define F2      512
#define NE      120
#define H1N     480
#define H2N     1920
#define HN      (N_NODES*EMBED)   // 30720

// ---------- scratch (device globals; no allocation) ----------
__device__ float g_h2[H2N];            // post-relu hidden 2
__device__ float g_H[HN];              // h@W3+b3 accumulator (init b3 in k_pre)
__device__ float g_HW1[N_NODES*F1];
__device__ float g_X1[N_NODES*F1];
__device__ float g_HW2[N_NODES*F2];
__device__ float g_X2[N_NODES*F2];
__device__ float g_m[F2];              // column mean of X2
__device__ float g_ctx[F2];            // accumulator for m@attW
__device__ int   g_cnt1[8];            // arrival counters gcn0 col tiles
__device__ int   g_cnt2[4];            // arrival counters gcn1 col tiles
__device__ float g_sink;               // DCE-prevention for prefetch

// =====================================================================
// K_PRE: fused  init + MLP1 + MLP2  (blocks 0..59)
//        and    accumulator init + gW1 L2 prefetch (blocks 60..147)
// =====================================================================
__global__ void __launch_bounds__(128) k_pre(
    const float* __restrict__ f,  const float* __restrict__ W1, const float* __restrict__ b1,
    const float* __restrict__ W2, const float* __restrict__ b2, const float* __restrict__ b3,
    const float* __restrict__ gW1) {
    int bx = blockIdx.x, t = threadIdx.x;
    if (bx < 60) {
        __shared__ float sf[N_NODES];
        __shared__ float sh1[H1N];
        __shared__ float red[4][32];
        if (t < N_NODES) sf[t] = f[t];
        __syncthreads();
        for (int j = t; j < H1N; j += 128) {
            float a = b1[j];
#pragma unroll
            for (int i = 0; i < N_NODES; i++) a += sf[i] * W1[i * H1N + j];
            sh1[j] = fmaxf(a, 0.f);
        }
        __syncthreads();
        int col = bx * 32 + (t & 31);
        int s   = t >> 5;                 // 4-way k-split of K=480
        int k0  = s * 120;
        float a = 0.f;
#pragma unroll 8
        for (int kk = 0; kk < 120; kk++)
            a += sh1[k0 + kk] * W2[(k0 + kk) * H2N + col];
        red[s][t & 31] = a;
        __syncthreads();
        if (s == 0) {
            float v = a + red[1][t] + red[2][t] + red[3][t] + b2[col];
            g_h2[col] = fmaxf(v, 0.f);    // relu here; mlp3 reads directly
        }
    } else {
        int gt = (bx - 60) * 128 + t;     // 0 .. 11263
        const int GS = 88 * 128;
        for (int i = gt; i < HN; i += GS)            g_H[i]   = b3[i];
        for (int i = gt; i < N_NODES * F1; i += GS)  g_HW1[i] = 0.f;
        for (int i = gt; i < N_NODES * F2; i += GS)  g_HW2[i] = 0.f;
        if (gt < F2) g_ctx[gt] = 0.f;
        if (gt < 8)  g_cnt1[gt] = 0;
        if (gt < 4)  g_cnt2[gt] = 0;

        // prefetch gW1 (8 MB) into L2, overlapped with the MLP blocks
        float4 av = make_float4(0.f, 0.f, 0.f, 0.f);
        const float4* p1 = (const float4*)gW1;   // 524288 float4
#pragma unroll 4
        for (int i = gt; i < 524288; i += GS) {
            float4 v = p1[i]; av.x += v.x; av.y += v.y; av.z += v.z; av.w += v.w;
        }
        float ssum = av.x + av.y + av.z + av.w;
        if (ssum == 1.234567e38f) g_sink = ssum;  // never true; blocks DCE
    }
}

// =====================================================================
// K_MLP3: g_H += relu(h2) @ W3   (split-K, float4, streaming loads)
// =====================================================================
__global__ void __launch_bounds__(128) k_mlp3(const float4* __restrict__ W3v) {
    __shared__ float sh[120];
    int t = threadIdx.x;
    int k0 = blockIdx.y * 120;
    if (t < 120) sh[t] = g_h2[k0 + t];
    __syncthreads();
    int c = blockIdx.x * 128 + t;            // 7680 float4 columns
    const float4* p = W3v + (size_t)k0 * 7680 + c;
    float4 acc = make_float4(0.f, 0.f, 0.f, 0.f);
#pragma unroll 8
    for (int kk = 0; kk < 120; kk++) {
        float4 w = __ldcs(p + (size_t)kk * 7680);   // evict-first streaming
        float h = sh[kk];
        acc.x += h * w.x; acc.y += h * w.y; acc.z += h * w.z; acc.w += h * w.w;
    }
    float* o = g_H + 4 * c;
    atomicAdd(o + 0, acc.x); atomicAdd(o + 1, acc.y);
    atomicAdd(o + 2, acc.z); atomicAdd(o + 3, acc.w);
}

// =====================================================================
// K_GCN: high-parallelism fused  (X @ W split-K)  +  adjacency agg
// Block tile: 128 cols x 128 k.  256 threads = 128 cols x 2 sub-k(64).
// Extra grid row (y == NY) prefetches next-stage weights into L2.
// L=0: g_H[15,2048]@gW1 -> relu agg -> g_X1 ; grid (8, 17)
// L=1: g_X1[15,1024]@gW2 -> agg+mean -> g_X2 ; grid (4, 9)
// =====================================================================
template <int L>
__global__ void __launch_bounds__(256) k_gcn(const float* __restrict__ W,
                                             const float* __restrict__ bias,
                                             const int* __restrict__ eidx,
                                             const float4* __restrict__ pf, int pfN) {
    constexpr int K  = (L == 0) ? 2048 : 1024;
    constexpr int N  = (L == 0) ? 1024 : 512;
    constexpr int NY = (L == 0) ? 16 : 8;       // k-splits of 128
    constexpr int NX = N / 128;
    const float* X  = (L == 0) ? g_H  : g_X1;
    float* OUT      = (L == 0) ? g_HW1 : g_HW2;
    float* XO       = (L == 0) ? g_X1 : g_X2;
    int*   cnt      = (L == 0) ? g_cnt1 : g_cnt2;

    int t = threadIdx.x;
    int x = blockIdx.x, y = blockIdx.y;

    if (y == NY) {   // ---- prefetch next-stage weights into L2 ----
        float4 av = make_float4(0.f, 0.f, 0.f, 0.f);
        for (int i = x * 256 + t; i < pfN; i += NX * 256) {
            float4 v = __ldg(pf + i);
            av.x += v.x; av.y += v.y; av.z += v.z; av.w += v.w;
        }
        float ssum = av.x + av.y + av.z + av.w;
        if (ssum == 1.234567e38f) g_sink = ssum;
        return;
    }

    __shared__ float Xt[N_NODES * 128];
    int k0 = y * 128;
    for (int idx = t; idx < N_NODES * 128; idx += 256) {
        int i = idx >> 7, kk = idx & 127;
        Xt[idx] = X[i * K + k0 + kk];
    }
    __syncthreads();

    int g  = t >> 7;          // sub-k group 0/1
    int jt = t & 127;
    int j  = x * 128 + jt;
    const float* wp = W + (size_t)(k0 + g * 64) * N + j;
    float acc[N_NODES];
#pragma unroll
    for (int i = 0; i < N_NODES; i++) acc[i] = 0.f;
#pragma unroll 8
    for (int kk = 0; kk < 64; kk++) {
        float w = __ldg(wp + (size_t)kk * N);
        const float* xr = &Xt[g * 64 + kk];
#pragma unroll
        for (int i = 0; i < N_NODES; i++) acc[i] += xr[i * 128] * w;
    }
    __syncthreads();                       // Xt reads complete
    if (g == 1) {
#pragma unroll
        for (int i = 0; i < N_NODES; i++) Xt[i * 128 + jt] = acc[i];
    }
    __syncthreads();
    if (g == 0) {
#pragma unroll
        for (int i = 0; i < N_NODES; i++)
            atomicAdd(&OUT[i * N + j], acc[i] + Xt[i * 128 + jt]);
    }

    // ---- arrival: last k-split block for this column tile aggregates ----
    __threadfence();
    __syncthreads();
    __shared__ int isLast;
    if (t == 0) isLast = (atomicAdd(&cnt[x], 1) == NY - 1);
    __syncthreads();
    if (!isLast) return;

    __shared__ int   se[NE], de[NE];
    __shared__ float degs[N_NODES], dinv[N_NODES], nrm[NE];
    __shared__ float hws[N_NODES][128];
    __shared__ float outs[N_NODES][128];
    if (t < NE) { se[t] = eidx[t]; de[t] = eidx[NE + t]; }
    if (t < N_NODES) degs[t] = 1.f;               // self loop
    __syncthreads();
    if (t < NE) atomicAdd(&degs[de[t]], 1.f);
    __syncthreads();
    if (t < N_NODES) dinv[t] = rsqrtf(degs[t]);
    __syncthreads();
    if (t < NE) nrm[t] = dinv[se[t]] * dinv[de[t]];
    if (t < 128) {
#pragma unroll
        for (int i = 0; i < N_NODES; i++) hws[i][t] = __ldcg(&OUT[i * N + x * 128 + t]);
    }
    __syncthreads();
    if (t < 128) {
        int jj = x * 128 + t;
#pragma unroll
        for (int i = 0; i < N_NODES; i++) outs[i][t] = hws[i][t] * dinv[i] * dinv[i];
        for (int e = 0; e < NE; e++)
            outs[de[e]][t] += hws[se[e]][t] * nrm[e];

        float b = bias[jj];
        float s = 0.f;
#pragma unroll
        for (int i = 0; i < N_NODES; i++) {
            float v = outs[i][t] + b;
            if (L == 0) v = fmaxf(v, 0.f);
            XO[i * N + jj] = v;
            s += v;
        }
        if (L == 1) g_m[jj] = s * (1.f / 15.f);
    }
}

// =====================================================================
// K_CTX: g_ctx += m @ attW (split-K; attW L2-resident from gcn1 prefetch)
// =====================================================================
__global__ void __launch_bounds__(256) k_ctx(const float* __restrict__ attW) {
    __shared__ float sm[32];
    int t = threadIdx.x;
    int k0 = blockIdx.y * 32;                // 16 k-splits over 512
    if (t < 32) sm[t] = g_m[k0 + t];
    __syncthreads();
    int j = blockIdx.x * 256 + t;            // 2 blocks -> 512 cols
    float a = 0.f;
#pragma unroll
    for (int kk = 0; kk < 32; kk++) a += sm[kk] * attW[(size_t)(k0 + kk) * F2 + j];
    atomicAdd(&g_ctx[j], a);
}

// =====================================================================
// K_FINAL: attention pool + fc + softmax + loss
// =====================================================================
__global__ void __launch_bounds__(512) k_final(const float* __restrict__ fcW,
                                               const float* __restrict__ fcb,
                                               const float* __restrict__ target,
                                               float* __restrict__ out) {
    __shared__ float ctx_s[F2];
    __shared__ float sc[N_NODES];
    __shared__ float lg[3];
    int t = threadIdx.x;                 // 512 threads
    ctx_s[t] = tanhf(g_ctx[t]);
    if (t < 3) lg[t] = fcb[t];
    __syncthreads();

    int w = t >> 5, l = t & 31;          // 16 warps
    if (w < N_NODES) {
        float v = 0.f;
#pragma unroll
        for (int q = 0; q < 16; q++) {
            int j = l + 32 * q;
            v += g_X2[w * F2 + j] * ctx_s[j];
        }
#pragma unroll
        for (int o = 16; o > 0; o >>= 1) v += __shfl_xor_sync(0xffffffffu, v, o);
        if (l == 0) sc[w] = 1.f / (1.f + expf(-v));
    }
    __syncthreads();

    float rep = 0.f;
#pragma unroll
    for (int i = 0; i < N_NODES; i++) rep += g_X2[i * F2 + t] * sc[i];

    float p0 = rep * fcW[t * 3 + 0];
    float p1 = rep * fcW[t * 3 + 1];
    float p2 = rep * fcW[t * 3 + 2];
#pragma unroll
    for (int o = 16; o > 0; o >>= 1) {
        p0 += __shfl_xor_sync(0xffffffffu, p0, o);
        p1 += __shfl_xor_sync(0xffffffffu, p1, o);
        p2 += __shfl_xor_sync(0xffffffffu, p2, o);
    }
    if (l == 0) { atomicAdd(&lg[0], p0); atomicAdd(&lg[1], p1); atomicAdd(&lg[2], p2); }
    __syncthreads();

    if (t == 0) {
        float l0 = lg[0], l1 = lg[1], l2 = lg[2];
        float mx = fmaxf(l0, fmaxf(l1, l2));
        float e0 = expf(l0 - mx), e1 = expf(l1 - mx), e2 = expf(l2 - mx);
        float s = e0 + e1 + e2;
        float t0 = target[0], t1 = target[1], t2 = target[2];
        int cls = 0; float tm = t0;
        if (t1 > tm) { tm = t1; cls = 1; }
        if (t2 > tm) { tm = t2; cls = 2; }
        float lcls = (cls == 0) ? l0 : ((cls == 1) ? l1 : l2);
        out[0] = -(lcls - mx - logf(s));    // loss
        out[1] = e0 / s; out[2] = e1 / s; out[3] = e2 / s;  // predictions
    }
}

// ---------- host ----------
extern "C" void kernel_launch(void* const* d_in, const int* in_sizes, int n_in,
                              void* d_out, int out_size) {
    const float* f      = (const float*)d_in[0];
    const int*   eidx   = (const int*)  d_in[1];
    const float* target = (const float*)d_in[2];
    const float* W1     = (const float*)d_in[3];
    const float* b1     = (const float*)d_in[4];
    const float* W2     = (const float*)d_in[5];
    const float* b2     = (const float*)d_in[6];
    const float* W3     = (const float*)d_in[7];
    const float* b3     = (const float*)d_in[8];
    const float* gW1    = (const float*)d_in[9];
    const float* gb1    = (const float*)d_in[10];
    const float* gW2    = (const float*)d_in[11];
    const float* gb2    = (const float*)d_in[12];
    const float* attW   = (const float*)d_in[13];
    const float* fcW    = (const float*)d_in[14];
    const float* fcb    = (const float*)d_in[15];
    float* out = (float*)d_out;

    k_pre <<<148, 128>>>(f, W1, b1, W2, b2, b3, gW1);
    k_mlp3<<<dim3(60, 16), 128>>>((const float4*)W3);
    k_gcn<0><<<dim3(8, 17), 256>>>(gW1, gb1, eidx, (const float4*)gW2, 131072);
    k_gcn<1><<<dim3(4, 9),  256>>>(gW2, gb2, eidx, (const float4*)attW, 65536);
    k_ctx <<<dim3(2, 16), 256>>>(attW);
    k_final<<<1, 512>>>(fcW, fcb, target, out);
}